// round 5
// baseline (speedup 1.0000x reference)
#include <cuda_runtime.h>
#include <cstdint>

// Scratch: projected Q (normalized, /8 folded), K (normalized), V — all stored
// pre-rounded to tf32 (RNA) so the attention kernel can consume raw bits.
__device__ float g_Q[8 * 2048 * 64];
__device__ float g_K[8 * 2048 * 64];
__device__ float g_V[8 * 2048 * 64];
// KV-split partial results (no max needed: logits bounded by 1/8)
__device__ float g_Op[2][8 * 2048 * 64];
__device__ float g_Lp[2][8 * 2048];

__device__ __forceinline__ uint32_t f2tf(float x) {
    uint32_t y;
    asm("cvt.rna.tf32.f32 %0, %1;" : "=r"(y) : "f"(x));
    return y;
}
__device__ __forceinline__ uint32_t u2tf(uint32_t xu) {
    uint32_t y;
    asm("cvt.rna.tf32.f32 %0, %1;" : "=r"(y) : "r"(xu));
    return y;
}

__device__ __forceinline__ void cp16(uint32_t dst_smem, const void* src) {
    asm volatile("cp.async.ca.shared.global [%0], [%1], 16;"
                 :: "r"(dst_smem), "l"(src));
}

// exp(x) for |x| <= ~0.13 : degree-4 Taylor, max err ~2.6e-8
__device__ __forceinline__ float exp_small(float x) {
    float t = fmaf(x, 0.041666667f, 0.16666667f);
    t = fmaf(t, x, 0.5f);
    t = fmaf(t, x, 1.0f);
    t = fmaf(t, x, 1.0f);
    return t;
}

__device__ __forceinline__ void mma_tf32(float d[4], const uint32_t a[4],
                                         const uint32_t b[2], const float c[4]) {
    asm volatile(
        "mma.sync.aligned.m16n8k8.row.col.f32.tf32.tf32.f32 "
        "{%0,%1,%2,%3}, {%4,%5,%6,%7}, {%8,%9}, {%10,%11,%12,%13};"
        : "=f"(d[0]), "=f"(d[1]), "=f"(d[2]), "=f"(d[3])
        : "r"(a[0]), "r"(a[1]), "r"(a[2]), "r"(a[3]),
          "r"(b[0]), "r"(b[1]),
          "f"(c[0]), "f"(c[1]), "f"(c[2]), "f"(c[3]));
}

// single shared-memory declaration for the whole TU
extern __shared__ char smem_raw[];

// ---------------------------------------------------------------------------
// Projection: out[16384,64] = X[16384,768] @ W[768,64] + bias, optional row
// L2-normalize; stores tf32-rounded. cp.async double-buffered raw fp32 tiles,
// cvt.rna applied after LDS (numerics identical to cvt-before-STS).
// Tiles: A[128][64] fp32 (row stride 68), B[64][64] fp32 (row stride 72).
// ---------------------------------------------------------------------------
#define PJ_A_STRIDE 68
#define PJ_B_STRIDE 72
#define PJ_A_SZ (128 * PJ_A_STRIDE)          // floats
#define PJ_B_SZ (64 * PJ_B_STRIDE)
#define PJ_BUF   (PJ_A_SZ + PJ_B_SZ)
#define PROJ_SMEM (2 * PJ_BUF * 4)

__global__ __launch_bounds__(128, 2) void proj_kernel(
    const float* __restrict__ Xq, const float* __restrict__ Wq, const float* __restrict__ bq,
    const float* __restrict__ Xk, const float* __restrict__ Wk, const float* __restrict__ bk,
    const float* __restrict__ Xv, const float* __restrict__ Wv, const float* __restrict__ bv)
{
    uint32_t* sm = (uint32_t*)smem_raw;
    const uint32_t sb = (uint32_t)__cvta_generic_to_shared(smem_raw);

    const int which = blockIdx.y;
    const float* X    = which == 0 ? Xq : which == 1 ? Xk : Xv;
    const float* W    = which == 0 ? Wq : which == 1 ? Wk : Wv;
    const float* bias = which == 0 ? bq : which == 1 ? bk : bv;
    float* out        = which == 0 ? g_Q : which == 1 ? g_K : g_V;
    const float post  = (which == 0) ? 0.125f : 1.0f;
    const bool do_norm = (which != 2);

    const int tid  = threadIdx.x;
    const int lane = tid & 31;
    const int warp = tid >> 5;
    const int g = lane >> 2, t = lane & 3;
    const int row0 = blockIdx.x * 128;
    const int wrow = warp * 32;

    float acc[2][8][4];
#pragma unroll
    for (int mf = 0; mf < 2; mf++)
#pragma unroll
        for (int nf = 0; nf < 8; nf++)
#pragma unroll
            for (int i = 0; i < 4; i++) acc[mf][nf][i] = 0.f;

    // issue tile kt into buffer p
    auto issue_tile = [&](int kt, int p) {
        const uint32_t aB = sb + p * PJ_BUF * 4;
        const uint32_t bB = aB + PJ_A_SZ * 4;
#pragma unroll
        for (int i = 0; i < 16; i++) {
            int idx = tid + i * 128;
            int r = idx >> 4, c4 = idx & 15;
            cp16(aB + (r * PJ_A_STRIDE + c4 * 4) * 4,
                 X + (size_t)(row0 + r) * 768 + kt * 64 + c4 * 4);
        }
#pragma unroll
        for (int i = 0; i < 8; i++) {
            int idx = tid + i * 128;
            int r = idx >> 4, c4 = idx & 15;
            cp16(bB + (r * PJ_B_STRIDE + c4 * 4) * 4,
                 W + (size_t)(kt * 64 + r) * 64 + c4 * 4);
        }
        asm volatile("cp.async.commit_group;");
    };

    issue_tile(0, 0);

    for (int kt = 0; kt < 12; kt++) {
        const int p = kt & 1;
        if (kt < 11) {
            issue_tile(kt + 1, p ^ 1);
            asm volatile("cp.async.wait_group 1;");
        } else {
            asm volatile("cp.async.wait_group 0;");
        }
        __syncthreads();

        const uint32_t* As = sm + p * PJ_BUF;
        const uint32_t* Bs = As + PJ_A_SZ;
#pragma unroll
        for (int k8 = 0; k8 < 8; k8++) {
            uint32_t bfr[8][2];
#pragma unroll
            for (int nf = 0; nf < 8; nf++) {
                bfr[nf][0] = u2tf(Bs[(k8 * 8 + t) * PJ_B_STRIDE + nf * 8 + g]);
                bfr[nf][1] = u2tf(Bs[(k8 * 8 + t + 4) * PJ_B_STRIDE + nf * 8 + g]);
            }
#pragma unroll
            for (int mf = 0; mf < 2; mf++) {
                uint32_t a[4];
                int rb = (wrow + mf * 16 + g) * PJ_A_STRIDE + k8 * 8 + t;
                a[0] = u2tf(As[rb]);
                a[1] = u2tf(As[rb + 8 * PJ_A_STRIDE]);
                a[2] = u2tf(As[rb + 4]);
                a[3] = u2tf(As[rb + 8 * PJ_A_STRIDE + 4]);
#pragma unroll
                for (int nf = 0; nf < 8; nf++) mma_tf32(acc[mf][nf], a, bfr[nf], acc[mf][nf]);
            }
        }
        __syncthreads();
    }

    // epilogue: bias, optional L2 row-normalize, store tf32-rounded
#pragma unroll
    for (int mf = 0; mf < 2; mf++) {
#pragma unroll
        for (int nf = 0; nf < 8; nf++) {
            float b0 = bias[nf * 8 + t * 2];
            float b1 = bias[nf * 8 + t * 2 + 1];
            acc[mf][nf][0] += b0; acc[mf][nf][1] += b1;
            acc[mf][nf][2] += b0; acc[mf][nf][3] += b1;
        }
        float s0 = 1.f, s1 = 1.f;
        if (do_norm) {
            float q0 = 0.f, q1 = 0.f;
#pragma unroll
            for (int nf = 0; nf < 8; nf++) {
                q0 += acc[mf][nf][0] * acc[mf][nf][0] + acc[mf][nf][1] * acc[mf][nf][1];
                q1 += acc[mf][nf][2] * acc[mf][nf][2] + acc[mf][nf][3] * acc[mf][nf][3];
            }
            q0 += __shfl_xor_sync(0xffffffffu, q0, 1);
            q0 += __shfl_xor_sync(0xffffffffu, q0, 2);
            q1 += __shfl_xor_sync(0xffffffffu, q1, 1);
            q1 += __shfl_xor_sync(0xffffffffu, q1, 2);
            s0 = rsqrtf(q0) * post;
            s1 = rsqrtf(q1) * post;
        }
        int ra = row0 + wrow + mf * 16 + g;
#pragma unroll
        for (int nf = 0; nf < 8; nf++) {
            float2 v0 = make_float2(__uint_as_float(f2tf(acc[mf][nf][0] * s0)),
                                    __uint_as_float(f2tf(acc[mf][nf][1] * s0)));
            float2 v1 = make_float2(__uint_as_float(f2tf(acc[mf][nf][2] * s1)),
                                    __uint_as_float(f2tf(acc[mf][nf][3] * s1)));
            *(float2*)(out + (size_t)ra * 64 + nf * 8 + t * 2) = v0;
            *(float2*)(out + (size_t)(ra + 8) * 64 + nf * 8 + t * 2) = v1;
        }
    }
}

// ---------------------------------------------------------------------------
// Flash attention, KV-split x2. Logits = cosine/8 are bounded in [-1/8, 1/8],
// so NO max subtraction / rescaling is needed: p = exp(s) via degree-4 poly,
// l accumulated thread-locally, reduced once at the end.
// ---------------------------------------------------------------------------
#define ATTN_SMEM ((128 * 68 + 64 * 68 + 64 * 72 + 128 * 68) * 4)

__global__ __launch_bounds__(128, 2) void attn_kernel()
{
    uint32_t* smem = (uint32_t*)smem_raw;
    uint32_t* Qs = smem;                              // [128][68]
    uint32_t* Ks = Qs + 128 * 68;                     // [64][68]
    uint32_t* Vs = Ks + 64 * 68;                      // [64][72]
    uint32_t* Ps = Vs + 64 * 72;                      // [128][68]
    const uint32_t sbb = (uint32_t)__cvta_generic_to_shared(smem_raw);
    const uint32_t QsB = sbb;
    const uint32_t KsB = sbb + 128 * 68 * 4;
    const uint32_t VsB = KsB + 64 * 68 * 4;

    const int tid  = threadIdx.x;
    const int lane = tid & 31;
    const int warp = tid >> 5;
    const int g = lane >> 2, t = lane & 3;
    const int b = blockIdx.y, qt = blockIdx.x, split = blockIdx.z;
    const int base_q = b * 2048 + qt * 128;
    const int wrow = warp * 32;

#pragma unroll
    for (int i = 0; i < 16; i++) {
        int idx = tid + i * 128;
        int rr = idx >> 4, cc = idx & 15;
        cp16(QsB + (rr * 68 + cc * 4) * 4, g_Q + (size_t)(base_q + rr) * 64 + cc * 4);
    }

    float o[2][8][4];
#pragma unroll
    for (int mf = 0; mf < 2; mf++)
#pragma unroll
        for (int nf = 0; nf < 8; nf++)
#pragma unroll
            for (int i = 0; i < 4; i++) o[mf][nf][i] = 0.f;
    float lacc[2][2] = {{0.f, 0.f}, {0.f, 0.f}};

    const int j0 = split * 16;
    for (int j = j0; j < j0 + 16; j++) {
        const int base_k = b * 2048 + j * 64;
        __syncthreads();
#pragma unroll
        for (int i = 0; i < 8; i++) {
            int idx = tid + i * 128;
            int r = idx >> 4, c4 = idx & 15;
            cp16(KsB + (r * 68 + c4 * 4) * 4, g_K + (size_t)(base_k + r) * 64 + c4 * 4);
            cp16(VsB + (r * 72 + c4 * 4) * 4, g_V + (size_t)(base_k + r) * 64 + c4 * 4);
        }
        asm volatile("cp.async.commit_group;");
        asm volatile("cp.async.wait_group 0;");
        __syncthreads();

        // S = Qn @ Kn^T   (logits pre-scaled by 1/8, |S| <= ~0.125)
        float s[2][8][4];
#pragma unroll
        for (int mf = 0; mf < 2; mf++)
#pragma unroll
            for (int nf = 0; nf < 8; nf++)
#pragma unroll
                for (int i = 0; i < 4; i++) s[mf][nf][i] = 0.f;
#pragma unroll
        for (int k8 = 0; k8 < 8; k8++) {
            uint32_t bfr[8][2];
#pragma unroll
            for (int nf = 0; nf < 8; nf++) {
                bfr[nf][0] = Ks[(nf * 8 + g) * 68 + k8 * 8 + t];
                bfr[nf][1] = Ks[(nf * 8 + g) * 68 + k8 * 8 + t + 4];
            }
#pragma unroll
            for (int mf = 0; mf < 2; mf++) {
                uint32_t a[4];
                int rb = (wrow + mf * 16 + g) * 68 + k8 * 8 + t;
                a[0] = Qs[rb];
                a[1] = Qs[rb + 8 * 68];
                a[2] = Qs[rb + 4];
                a[3] = Qs[rb + 8 * 68 + 4];
#pragma unroll
                for (int nf = 0; nf < 8; nf++) mma_tf32(s[mf][nf], a, bfr[nf], s[mf][nf]);
            }
        }

        // p = exp(s) (poly), accumulate l locally, stage P to smem
#pragma unroll
        for (int mf = 0; mf < 2; mf++) {
            int prow = (wrow + mf * 16 + g) * 68;
            float rs0 = 0.f, rs1 = 0.f;
#pragma unroll
            for (int nf = 0; nf < 8; nf++) {
                float p0 = exp_small(s[mf][nf][0]);
                float p1 = exp_small(s[mf][nf][1]);
                float p2 = exp_small(s[mf][nf][2]);
                float p3 = exp_small(s[mf][nf][3]);
                rs0 += p0 + p1;
                rs1 += p2 + p3;
                Ps[prow + nf * 8 + t * 2]              = f2tf(p0);
                Ps[prow + nf * 8 + t * 2 + 1]          = f2tf(p1);
                Ps[prow + 8 * 68 + nf * 8 + t * 2]     = f2tf(p2);
                Ps[prow + 8 * 68 + nf * 8 + t * 2 + 1] = f2tf(p3);
            }
            lacc[mf][0] += rs0;
            lacc[mf][1] += rs1;
        }
        __syncwarp();

        // O += P @ V (no rescaling ever needed)
#pragma unroll
        for (int k8 = 0; k8 < 8; k8++) {
            uint32_t bfr[8][2];
#pragma unroll
            for (int nf = 0; nf < 8; nf++) {
                bfr[nf][0] = Vs[(k8 * 8 + t) * 72 + nf * 8 + g];
                bfr[nf][1] = Vs[(k8 * 8 + t + 4) * 72 + nf * 8 + g];
            }
#pragma unroll
            for (int mf = 0; mf < 2; mf++) {
                uint32_t a[4];
                int rb = (wrow + mf * 16 + g) * 68 + k8 * 8 + t;
                a[0] = Ps[rb];
                a[1] = Ps[rb + 8 * 68];
                a[2] = Ps[rb + 4];
                a[3] = Ps[rb + 8 * 68 + 4];
#pragma unroll
                for (int nf = 0; nf < 8; nf++) mma_tf32(o[mf][nf], a, bfr[nf], o[mf][nf]);
            }
        }
        __syncwarp();
    }

    // epilogue: store unnormalized partial O and per-row l
    float* Op = g_Op[split];
    float* Lp = g_Lp[split];
#pragma unroll
    for (int mf = 0; mf < 2; mf++) {
        float l0 = lacc[mf][0];
        float l1 = lacc[mf][1];
        l0 += __shfl_xor_sync(0xffffffffu, l0, 1);
        l0 += __shfl_xor_sync(0xffffffffu, l0, 2);
        l1 += __shfl_xor_sync(0xffffffffu, l1, 1);
        l1 += __shfl_xor_sync(0xffffffffu, l1, 2);
        int ra = base_q + wrow + mf * 16 + g;
        if (t == 0) {
            Lp[ra]     = l0;
            Lp[ra + 8] = l1;
        }
#pragma unroll
        for (int nf = 0; nf < 8; nf++) {
            float2 v0 = make_float2(o[mf][nf][0], o[mf][nf][1]);
            float2 v1 = make_float2(o[mf][nf][2], o[mf][nf][3]);
            *(float2*)(Op + (size_t)ra * 64 + nf * 8 + t * 2) = v0;
            *(float2*)(Op + (size_t)(ra + 8) * 64 + nf * 8 + t * 2) = v1;
        }
    }
}

// ---------------------------------------------------------------------------
// Combine the two KV-split partials: out = (o1 + o2) / (l1 + l2)
// ---------------------------------------------------------------------------
__global__ __launch_bounds__(256) void combine_kernel(float* __restrict__ out)
{
    int vid = blockIdx.x * 256 + threadIdx.x;   // 262144 float4s
    int row = vid >> 4;
    int c4  = vid & 15;
    float inv = 1.f / (g_Lp[0][row] + g_Lp[1][row]);
    const float4 o1 = *(const float4*)(&g_Op[0][(size_t)row * 64 + c4 * 4]);
    const float4 o2 = *(const float4*)(&g_Op[1][(size_t)row * 64 + c4 * 4]);
    float4 r;
    r.x = (o1.x + o2.x) * inv;
    r.y = (o1.y + o2.y) * inv;
    r.z = (o1.z + o2.z) * inv;
    r.w = (o1.w + o2.w) * inv;
    *(float4*)(out + (size_t)vid * 4) = r;
}

extern "C" void kernel_launch(void* const* d_in, const int* in_sizes, int n_in,
                              void* d_out, int out_size)
{
    const float* query = (const float*)d_in[0];
    const float* key   = (const float*)d_in[1];
    const float* value = (const float*)d_in[2];
    const float* Wq    = (const float*)d_in[3];
    const float* bq    = (const float*)d_in[4];
    const float* Wk    = (const float*)d_in[5];
    const float* bk    = (const float*)d_in[6];
    const float* Wv    = (const float*)d_in[7];
    const float* bv    = (const float*)d_in[8];

    cudaFuncSetAttribute(proj_kernel, cudaFuncAttributeMaxDynamicSharedMemorySize, PROJ_SMEM);
    cudaFuncSetAttribute(attn_kernel, cudaFuncAttributeMaxDynamicSharedMemorySize, ATTN_SMEM);

    proj_kernel<<<dim3(128, 3), 128, PROJ_SMEM>>>(query, Wq, bq, key, Wk, bk, value, Wv, bv);
    attn_kernel<<<dim3(16, 8, 2), 128, ATTN_SMEM>>>();
    combine_kernel<<<1024, 256>>>((float*)d_out);
}

// round 6
// speedup vs baseline: 1.0845x; 1.0845x over previous
#include <cuda_runtime.h>
#include <cstdint>

// Scratch: projected Q (normalized, /8 folded), K (normalized), V — all stored
// pre-rounded to tf32 (RNA) so the attention kernel can consume raw bits.
__device__ float g_Q[8 * 2048 * 64];
__device__ float g_K[8 * 2048 * 64];
__device__ float g_V[8 * 2048 * 64];
// KV-split partial results (no max needed: logits bounded by 1/8)
__device__ float g_Op[2][8 * 2048 * 64];
__device__ float g_Lp[2][8 * 2048];

__device__ __forceinline__ uint32_t f2tf(float x) {
    uint32_t y;
    asm("cvt.rna.tf32.f32 %0, %1;" : "=r"(y) : "f"(x));
    return y;
}

__device__ __forceinline__ void cp16(uint32_t dst_smem, const void* src) {
    asm volatile("cp.async.ca.shared.global [%0], [%1], 16;"
                 :: "r"(dst_smem), "l"(src));
}

// exp(x) for |x| <= ~0.13 : degree-4 Taylor, max err ~2.6e-8
__device__ __forceinline__ float exp_small(float x) {
    float t = fmaf(x, 0.041666667f, 0.16666667f);
    t = fmaf(t, x, 0.5f);
    t = fmaf(t, x, 1.0f);
    t = fmaf(t, x, 1.0f);
    return t;
}

__device__ __forceinline__ void mma_tf32(float d[4], const uint32_t a[4],
                                         const uint32_t b[2], const float c[4]) {
    asm volatile(
        "mma.sync.aligned.m16n8k8.row.col.f32.tf32.tf32.f32 "
        "{%0,%1,%2,%3}, {%4,%5,%6,%7}, {%8,%9}, {%10,%11,%12,%13};"
        : "=f"(d[0]), "=f"(d[1]), "=f"(d[2]), "=f"(d[3])
        : "r"(a[0]), "r"(a[1]), "r"(a[2]), "r"(a[3]),
          "r"(b[0]), "r"(b[1]),
          "f"(c[0]), "f"(c[1]), "f"(c[2]), "f"(c[3]));
}

// single shared-memory declaration for the whole TU
extern __shared__ char smem_raw[];

// ---------------------------------------------------------------------------
// Projection (R1 structure): out[16384,64] = X @ W + bias, optional row
// L2-normalize; stores tf32-rounded. Sync loads, cvt before STS, no reg cap.
// ---------------------------------------------------------------------------
#define PROJ_SMEM ((128 * 68 + 64 * 72) * 4)

__global__ __launch_bounds__(128, 1) void proj_kernel(
    const float* __restrict__ Xq, const float* __restrict__ Wq, const float* __restrict__ bq,
    const float* __restrict__ Xk, const float* __restrict__ Wk, const float* __restrict__ bk,
    const float* __restrict__ Xv, const float* __restrict__ Wv, const float* __restrict__ bv)
{
    uint32_t* As = (uint32_t*)smem_raw;  // [128][68]
    uint32_t* Bs = As + 128 * 68;        // [64][72]

    const int which = blockIdx.y;
    const float* X    = which == 0 ? Xq : which == 1 ? Xk : Xv;
    const float* W    = which == 0 ? Wq : which == 1 ? Wk : Wv;
    const float* bias = which == 0 ? bq : which == 1 ? bk : bv;
    float* out        = which == 0 ? g_Q : which == 1 ? g_K : g_V;
    const float post  = (which == 0) ? 0.125f : 1.0f;
    const bool do_norm = (which != 2);

    const int tid  = threadIdx.x;
    const int lane = tid & 31;
    const int warp = tid >> 5;
    const int g = lane >> 2, t = lane & 3;
    const int row0 = blockIdx.x * 128;
    const int wrow = warp * 32;

    float acc[2][8][4];
#pragma unroll
    for (int mf = 0; mf < 2; mf++)
#pragma unroll
        for (int nf = 0; nf < 8; nf++)
#pragma unroll
            for (int i = 0; i < 4; i++) acc[mf][nf][i] = 0.f;

    for (int kt = 0; kt < 12; kt++) {
#pragma unroll
        for (int i = 0; i < 16; i++) {
            int idx = tid + i * 128;
            int r = idx >> 4, c4 = idx & 15;
            float4 v = *(const float4*)(X + (size_t)(row0 + r) * 768 + kt * 64 + c4 * 4);
            uint32_t* dst = &As[r * 68 + c4 * 4];
            dst[0] = f2tf(v.x); dst[1] = f2tf(v.y); dst[2] = f2tf(v.z); dst[3] = f2tf(v.w);
        }
#pragma unroll
        for (int i = 0; i < 8; i++) {
            int idx = tid + i * 128;
            int r = idx >> 4, c4 = idx & 15;
            float4 v = *(const float4*)(W + (size_t)(kt * 64 + r) * 64 + c4 * 4);
            uint32_t* dst = &Bs[r * 72 + c4 * 4];
            dst[0] = f2tf(v.x); dst[1] = f2tf(v.y); dst[2] = f2tf(v.z); dst[3] = f2tf(v.w);
        }
        __syncthreads();
#pragma unroll
        for (int k8 = 0; k8 < 8; k8++) {
            uint32_t bfr[8][2];
#pragma unroll
            for (int nf = 0; nf < 8; nf++) {
                bfr[nf][0] = Bs[(k8 * 8 + t) * 72 + nf * 8 + g];
                bfr[nf][1] = Bs[(k8 * 8 + t + 4) * 72 + nf * 8 + g];
            }
#pragma unroll
            for (int mf = 0; mf < 2; mf++) {
                uint32_t a[4];
                int rb = (wrow + mf * 16 + g) * 68 + k8 * 8 + t;
                a[0] = As[rb];
                a[1] = As[rb + 8 * 68];
                a[2] = As[rb + 4];
                a[3] = As[rb + 8 * 68 + 4];
#pragma unroll
                for (int nf = 0; nf < 8; nf++) mma_tf32(acc[mf][nf], a, bfr[nf], acc[mf][nf]);
            }
        }
        __syncthreads();
    }

#pragma unroll
    for (int mf = 0; mf < 2; mf++) {
#pragma unroll
        for (int nf = 0; nf < 8; nf++) {
            float b0 = bias[nf * 8 + t * 2];
            float b1 = bias[nf * 8 + t * 2 + 1];
            acc[mf][nf][0] += b0; acc[mf][nf][1] += b1;
            acc[mf][nf][2] += b0; acc[mf][nf][3] += b1;
        }
        float s0 = 1.f, s1 = 1.f;
        if (do_norm) {
            float q0 = 0.f, q1 = 0.f;
#pragma unroll
            for (int nf = 0; nf < 8; nf++) {
                q0 += acc[mf][nf][0] * acc[mf][nf][0] + acc[mf][nf][1] * acc[mf][nf][1];
                q1 += acc[mf][nf][2] * acc[mf][nf][2] + acc[mf][nf][3] * acc[mf][nf][3];
            }
            q0 += __shfl_xor_sync(0xffffffffu, q0, 1);
            q0 += __shfl_xor_sync(0xffffffffu, q0, 2);
            q1 += __shfl_xor_sync(0xffffffffu, q1, 1);
            q1 += __shfl_xor_sync(0xffffffffu, q1, 2);
            s0 = rsqrtf(q0) * post;
            s1 = rsqrtf(q1) * post;
        }
        int ra = row0 + wrow + mf * 16 + g;
#pragma unroll
        for (int nf = 0; nf < 8; nf++) {
            float2 v0 = make_float2(__uint_as_float(f2tf(acc[mf][nf][0] * s0)),
                                    __uint_as_float(f2tf(acc[mf][nf][1] * s0)));
            float2 v1 = make_float2(__uint_as_float(f2tf(acc[mf][nf][2] * s1)),
                                    __uint_as_float(f2tf(acc[mf][nf][3] * s1)));
            *(float2*)(out + (size_t)ra * 64 + nf * 8 + t * 2) = v0;
            *(float2*)(out + (size_t)(ra + 8) * 64 + nf * 8 + t * 2) = v1;
        }
    }
}

// ---------------------------------------------------------------------------
// Flash attention, KV-split x2, Q-fragments hoisted to registers,
// K/V double-buffered with cp.async 2-stage pipeline. No softmax max needed
// (|logit| <= 1/8): p = poly exp, l accumulated locally.
// smem layout (bytes): buf0 K[64][68] V[64][72], buf1 K V, P[128][68]
// ---------------------------------------------------------------------------
#define KSZ  (64 * 68 * 4)
#define VSZ  (64 * 72 * 4)
#define PAIR (KSZ + VSZ)               // 35840
#define POFF (2 * PAIR)                // 71680
#define ATTN_SMEM (POFF + 128 * 68 * 4)  // 106496

__global__ __launch_bounds__(128, 2) void attn_kernel()
{
    uint32_t* smem = (uint32_t*)smem_raw;
    const uint32_t sbb = (uint32_t)__cvta_generic_to_shared(smem_raw);
    uint32_t* Ps = smem + POFF / 4;

    const int tid  = threadIdx.x;
    const int lane = tid & 31;
    const int warp = tid >> 5;
    const int g = lane >> 2, t = lane & 3;
    const int b = blockIdx.y, qt = blockIdx.x, split = blockIdx.z;
    const int base_q = b * 2048 + qt * 128;
    const int wrow = warp * 32;
    const int j0 = split * 16;

    // ---- stage Q into buf0 region (fits: 34816 <= 35840), read frags, free it
#pragma unroll
    for (int i = 0; i < 16; i++) {
        int idx = tid + i * 128;
        int rr = idx >> 4, cc = idx & 15;
        cp16(sbb + (rr * 68 + cc * 4) * 4, g_Q + (size_t)(base_q + rr) * 64 + cc * 4);
    }
    asm volatile("cp.async.commit_group;");
    asm volatile("cp.async.wait_group 0;");
    __syncthreads();

    uint32_t qa[8][2][4];   // [k8][mf][frag]
#pragma unroll
    for (int k8 = 0; k8 < 8; k8++)
#pragma unroll
        for (int mf = 0; mf < 2; mf++) {
            int rb = (wrow + mf * 16 + g) * 68 + k8 * 8 + t;
            qa[k8][mf][0] = smem[rb];
            qa[k8][mf][1] = smem[rb + 8 * 68];
            qa[k8][mf][2] = smem[rb + 4];
            qa[k8][mf][3] = smem[rb + 8 * 68 + 4];
        }
    __syncthreads();   // all Q reads done before K/V overwrite buf0

    // ---- K/V pipeline
    auto issue_kv = [&](int j, int p) {
        const int base_k = b * 2048 + j * 64;
        const uint32_t kB = sbb + p * PAIR;
        const uint32_t vB = kB + KSZ;
#pragma unroll
        for (int i = 0; i < 8; i++) {
            int idx = tid + i * 128;
            int r = idx >> 4, c4 = idx & 15;
            cp16(kB + (r * 68 + c4 * 4) * 4, g_K + (size_t)(base_k + r) * 64 + c4 * 4);
            cp16(vB + (r * 72 + c4 * 4) * 4, g_V + (size_t)(base_k + r) * 64 + c4 * 4);
        }
        asm volatile("cp.async.commit_group;");
    };

    issue_kv(j0, 0);
    issue_kv(j0 + 1, 1);

    float o[2][8][4];
#pragma unroll
    for (int mf = 0; mf < 2; mf++)
#pragma unroll
        for (int nf = 0; nf < 8; nf++)
#pragma unroll
            for (int i = 0; i < 4; i++) o[mf][nf][i] = 0.f;
    float lacc[2][2] = {{0.f, 0.f}, {0.f, 0.f}};

    for (int i = 0; i < 16; i++) {
        const int p = i & 1;
        const uint32_t* Ks = smem + (p * PAIR) / 4;
        const uint32_t* Vs = Ks + KSZ / 4;

        if (i < 15) { asm volatile("cp.async.wait_group 1;"); }
        else        { asm volatile("cp.async.wait_group 0;"); }
        __syncthreads();

        // S = Qn @ Kn^T   (|S| <= ~0.125)
        float s[2][8][4];
#pragma unroll
        for (int mf = 0; mf < 2; mf++)
#pragma unroll
            for (int nf = 0; nf < 8; nf++)
#pragma unroll
                for (int q = 0; q < 4; q++) s[mf][nf][q] = 0.f;
#pragma unroll
        for (int k8 = 0; k8 < 8; k8++) {
            uint32_t bfr[8][2];
#pragma unroll
            for (int nf = 0; nf < 8; nf++) {
                bfr[nf][0] = Ks[(nf * 8 + g) * 68 + k8 * 8 + t];
                bfr[nf][1] = Ks[(nf * 8 + g) * 68 + k8 * 8 + t + 4];
            }
#pragma unroll
            for (int mf = 0; mf < 2; mf++)
#pragma unroll
                for (int nf = 0; nf < 8; nf++)
                    mma_tf32(s[mf][nf], qa[k8][mf], bfr[nf], s[mf][nf]);
        }

        // p = exp(s) (poly), accumulate l locally, stage P to smem
#pragma unroll
        for (int mf = 0; mf < 2; mf++) {
            int prow = (wrow + mf * 16 + g) * 68;
            float rs0 = 0.f, rs1 = 0.f;
#pragma unroll
            for (int nf = 0; nf < 8; nf++) {
                float p0 = exp_small(s[mf][nf][0]);
                float p1 = exp_small(s[mf][nf][1]);
                float p2 = exp_small(s[mf][nf][2]);
                float p3 = exp_small(s[mf][nf][3]);
                rs0 += p0 + p1;
                rs1 += p2 + p3;
                Ps[prow + nf * 8 + t * 2]              = f2tf(p0);
                Ps[prow + nf * 8 + t * 2 + 1]          = f2tf(p1);
                Ps[prow + 8 * 68 + nf * 8 + t * 2]     = f2tf(p2);
                Ps[prow + 8 * 68 + nf * 8 + t * 2 + 1] = f2tf(p3);
            }
            lacc[mf][0] += rs0;
            lacc[mf][1] += rs1;
        }
        __syncwarp();

        // O += P @ V
#pragma unroll
        for (int k8 = 0; k8 < 8; k8++) {
            uint32_t bfr[8][2];
#pragma unroll
            for (int nf = 0; nf < 8; nf++) {
                bfr[nf][0] = Vs[(k8 * 8 + t) * 72 + nf * 8 + g];
                bfr[nf][1] = Vs[(k8 * 8 + t + 4) * 72 + nf * 8 + g];
            }
#pragma unroll
            for (int mf = 0; mf < 2; mf++) {
                uint32_t a[4];
                int rb = (wrow + mf * 16 + g) * 68 + k8 * 8 + t;
                a[0] = Ps[rb];
                a[1] = Ps[rb + 8 * 68];
                a[2] = Ps[rb + 4];
                a[3] = Ps[rb + 8 * 68 + 4];
#pragma unroll
                for (int nf = 0; nf < 8; nf++) mma_tf32(o[mf][nf], a, bfr[nf], o[mf][nf]);
            }
        }
        __syncthreads();   // everyone done reading buffer p
        if (i + 2 < 16) issue_kv(j0 + i + 2, p);
    }

    // epilogue: store unnormalized partial O and per-row l
    float* Op = g_Op[split];
    float* Lp = g_Lp[split];
#pragma unroll
    for (int mf = 0; mf < 2; mf++) {
        float l0 = lacc[mf][0];
        float l1 = lacc[mf][1];
        l0 += __shfl_xor_sync(0xffffffffu, l0, 1);
        l0 += __shfl_xor_sync(0xffffffffu, l0, 2);
        l1 += __shfl_xor_sync(0xffffffffu, l1, 1);
        l1 += __shfl_xor_sync(0xffffffffu, l1, 2);
        int ra = base_q + wrow + mf * 16 + g;
        if (t == 0) {
            Lp[ra]     = l0;
            Lp[ra + 8] = l1;
        }
#pragma unroll
        for (int nf = 0; nf < 8; nf++) {
            float2 v0 = make_float2(o[mf][nf][0], o[mf][nf][1]);
            float2 v1 = make_float2(o[mf][nf][2], o[mf][nf][3]);
            *(float2*)(Op + (size_t)ra * 64 + nf * 8 + t * 2) = v0;
            *(float2*)(Op + (size_t)(ra + 8) * 64 + nf * 8 + t * 2) = v1;
        }
    }
}

// ---------------------------------------------------------------------------
// Combine the two KV-split partials: out = (o1 + o2) / (l1 + l2)
// ---------------------------------------------------------------------------
__global__ __launch_bounds__(256) void combine_kernel(float* __restrict__ out)
{
    int vid = blockIdx.x * 256 + threadIdx.x;   // 262144 float4s
    int row = vid >> 4;
    int c4  = vid & 15;
    float inv = 1.f / (g_Lp[0][row] + g_Lp[1][row]);
    const float4 o1 = *(const float4*)(&g_Op[0][(size_t)row * 64 + c4 * 4]);
    const float4 o2 = *(const float4*)(&g_Op[1][(size_t)row * 64 + c4 * 4]);
    float4 r;
    r.x = (o1.x + o2.x) * inv;
    r.y = (o1.y + o2.y) * inv;
    r.z = (o1.z + o2.z) * inv;
    r.w = (o1.w + o2.w) * inv;
    *(float4*)(out + (size_t)vid * 4) = r;
}

extern "C" void kernel_launch(void* const* d_in, const int* in_sizes, int n_in,
                              void* d_out, int out_size)
{
    const float* query = (const float*)d_in[0];
    const float* key   = (const float*)d_in[1];
    const float* value = (const float*)d_in[2];
    const float* Wq    = (const float*)d_in[3];
    const float* bq    = (const float*)d_in[4];
    const float* Wk    = (const float*)d_in[5];
    const float* bk    = (const float*)d_in[6];
    const float* Wv    = (const float*)d_in[7];
    const float* bv    = (const float*)d_in[8];

    cudaFuncSetAttribute(proj_kernel, cudaFuncAttributeMaxDynamicSharedMemorySize, PROJ_SMEM);
    cudaFuncSetAttribute(attn_kernel, cudaFuncAttributeMaxDynamicSharedMemorySize, ATTN_SMEM);

    proj_kernel<<<dim3(128, 3), 128, PROJ_SMEM>>>(query, Wq, bq, key, Wk, bk, value, Wv, bv);
    attn_kernel<<<dim3(16, 8, 2), 128, ATTN_SMEM>>>();
    combine_kernel<<<1024, 256>>>((float*)d_out);
}